// round 16
// baseline (speedup 1.0000x reference)
#include <cuda_runtime.h>
#include <math.h>

#define N_ELEMS 16384
#define NBINS   4096
#define NCTA    64
#define TPB     256
#define BPT     (NBINS / TPB)          // 16 bins per thread
#define JPT     (N_ELEMS / TPB)        // 64 j-elements per thread
#define DELTA_F 0.1f
#define EPS_F   1e-12f
#define FIX_SCALE 4294967296.0         // 2^32

// Dynamic smem layout (128B-aligned sections)
#define PREF_OFF 0                      // (NBINS+8) ints  = 16416 B
#define CURS_OFF 16512                  // NBINS ints      = 16384 B
#define G_OFF    32896                  // N_ELEMS floats  = 65536 B
#define SORT_OFF 98432                  // N_ELEMS floats  = 65536 B
#define SMEM_TOTAL_BYTES (SORT_OFF + N_ELEMS * 4)   // 163968 B

// ---- scratch (__device__ globals; zero-initialized at load) ----------------
__device__ float d_g[N_ELEMS];                // raw g values (plain stores)
__device__ unsigned long long d_accum;        // invariant: zero at launch entry
__device__ int   d_done;                      // invariant: zero at launch entry
__device__ volatile int d_sense;
__device__ int   d_barcnt;

__device__ __forceinline__ int warp_iscan(int v) {
#pragma unroll
    for (int o = 1; o < 32; o <<= 1) {
        int n = __shfl_up_sync(0xffffffffu, v, o);
        if ((threadIdx.x & 31) >= o) v += n;
    }
    return v;
}

__global__ __launch_bounds__(TPB)
void ghm_fused(const float* __restrict__ logits,
               const float* __restrict__ targets,
               float* __restrict__ out) {
    extern __shared__ char smem[];
    int*   s_pref   = (int*)(smem + PREF_OFF);   // hist -> exclusive prefix
    int*   s_curs   = (int*)(smem + CURS_OFF);   // scatter cursors
    float* s_g      = (float*)(smem + G_OFF);    // all 16K g values
    float* s_sorted = (float*)(smem + SORT_OFF); // bin-sorted g values
    __shared__ int s_wsum[8];
    __shared__ unsigned long long s_acc[8];

    const int t   = threadIdx.x;
    const int bid = blockIdx.x;
    const int i   = bid * TPB + t;     // this thread owns element i throughout

    int ls = d_sense;

    // ---- P0: prep g, plain store (no global atomics) ----
    float x  = logits[i];
    float tv = targets[i];
    float pred = 1.0f / (1.0f + __expf(-x));
    float g    = fabsf(pred - tv);
    d_g[i] = g;

    // ---- B1 arrive (the ONLY grid sync; loss computed in its shadow) ----
    __syncthreads();
    int arr = -1;
    if (t == 0) { __threadfence(); arr = atomicAdd(&d_barcnt, 1); }

    float loss = fmaxf(x, 0.0f) - x * tv + log1pf(__expf(-fabsf(x)));

    // ---- B1 wait ----
    if (t == 0) {
        if (arr == NCTA - 1) { d_barcnt = 0; __threadfence(); d_sense = 1 - ls; }
        else { while (d_sense == ls) { } __threadfence(); }
    }
    __syncthreads();

    // ---- stage all g into smem (coalesced) + zero the local histogram ----
    {
        const float4* src = (const float4*)d_g;
        float4*       dst = (float4*)s_g;
#pragma unroll
        for (int k = 0; k < N_ELEMS / 4 / TPB; k++)     // 16 x LDG.128
            dst[k * TPB + t] = src[k * TPB + t];
        int4 z = make_int4(0, 0, 0, 0);
#pragma unroll
        for (int k = 0; k < NBINS / 4 / TPB; k++)       // 4 x STS.128
            ((int4*)s_pref)[k * TPB + t] = z;
    }
    __syncthreads();

    // ---- local pass 1: histogram via smem atomics (spread addresses) ----
#pragma unroll 8
    for (int k = 0; k < JPT; k++) {
        float gj = s_g[k * TPB + t];
        int b = min((int)(gj * (float)NBINS), NBINS - 1);
        atomicAdd(&s_pref[b], 1);
    }
    __syncthreads();

    // ---- local scan: in-place exclusive prefix; cursor copy ----
    {
        int h[BPT];
        const int4* hv = (const int4*)&s_pref[t * BPT];
#pragma unroll
        for (int q = 0; q < BPT / 4; q++) {             // 4 x LDS.128
            int4 a = hv[q];
            h[q * 4 + 0] = a.x; h[q * 4 + 1] = a.y;
            h[q * 4 + 2] = a.z; h[q * 4 + 3] = a.w;
        }
        int tot = 0;
#pragma unroll
        for (int k = 0; k < BPT; k++) tot += h[k];
        int incl = warp_iscan(tot);
        if ((t & 31) == 31) s_wsum[t >> 5] = incl;
        __syncthreads();
        if (t < 8) {
            int w = s_wsum[t];
#pragma unroll
            for (int o = 1; o < 8; o <<= 1) {
                int n = __shfl_up_sync(0xffu, w, o);
                if (t >= o) w += n;
            }
            s_wsum[t] = w;
        }
        __syncthreads();
        int base = incl - tot + ((t >> 5) ? s_wsum[(t >> 5) - 1] : 0);
#pragma unroll
        for (int q = 0; q < BPT / 4; q++) {
            int4 pr;
            pr.x = base;               base += h[q * 4 + 0];
            pr.y = base;               base += h[q * 4 + 1];
            pr.z = base;               base += h[q * 4 + 2];
            pr.w = base;               base += h[q * 4 + 3];
            ((int4*)&s_pref[t * BPT])[q] = pr;          // overwrite own bins
            ((int4*)&s_curs[t * BPT])[q] = pr;          // cursor copy
        }
        if (t == TPB - 1) s_pref[NBINS] = N_ELEMS;
    }
    __syncthreads();

    // ---- local pass 2: scatter into bin-sorted smem array ----
#pragma unroll 8
    for (int k = 0; k < JPT; k++) {
        float gj = s_g[k * TPB + t];
        int b = min((int)(gj * (float)NBINS), NBINS - 1);
        int slot = atomicAdd(&s_curs[b], 1);
        s_sorted[slot] = gj;
    }
    __syncthreads();

    // ---- query own element ----
    // Interior bins [loBin+3, hiBin-3] guaranteed all-pass (>=1 bin-width
    // margin vs fp32 compare fuzz); bins outside [loBin-2, hiBin+2] guaranteed
    // all-fail; edge windows checked with the reference's exact fp32 compare.
    unsigned long long fixterm;
    {
        float p = g * (float)NBINS;
        int loBin = (int)floorf(p - 0.1f * (float)NBINS);
        int hiBin = (int)floorf(p + 0.1f * (float)NBINS);

        int iLo = min(max(loBin + 3, 0), NBINS);
        int iHi = min(max(hiBin - 2, 0), NBINS);
        int cnt = (iHi > iLo) ? (s_pref[iHi] - s_pref[iLo]) : 0;

        int a0 = max(loBin - 2, 0), b0 = min(loBin + 2, NBINS - 1);
        if (b0 >= a0) {
            int s = s_pref[a0], e = s_pref[b0 + 1];
#pragma unroll 8
            for (int idx = s; idx < e; idx++)
                cnt += (fabsf(s_sorted[idx] - g) <= DELTA_F) ? 1 : 0;
        }
        int a1 = max(hiBin - 2, 0), b1 = min(hiBin + 2, NBINS - 1);
        if (b1 >= a1) {
            int s = s_pref[a1], e = s_pref[b1 + 1];
#pragma unroll 8
            for (int idx = s; idx < e; idx++)
                cnt += (fabsf(s_sorted[idx] - g) <= DELTA_F) ? 1 : 0;
        }

        float GD   = (float)cnt / DELTA_F;
        float beta = (float)N_ELEMS / (GD + EPS_F);
        float term = beta * loss;      // >= 0
        fixterm = (unsigned long long)((double)term * FIX_SCALE);
    }

    // ---- deterministic finalize (u64 fixed-point; flat ticket) ----
    {
        unsigned long long v = fixterm;
#pragma unroll
        for (int off = 16; off > 0; off >>= 1)
            v += __shfl_down_sync(0xffffffffu, v, off);
        if ((t & 31) == 0) s_acc[t >> 5] = v;
        __syncthreads();
        if (t == 0) {
            unsigned long long w = 0;
#pragma unroll
            for (int k = 0; k < TPB / 32; k++) w += s_acc[k];
            atomicAdd(&d_accum, w);
            __threadfence();
            if (atomicAdd(&d_done, 1) == NCTA - 1) {
                __threadfence();
                unsigned long long total = atomicAdd(&d_accum, 0ULL);
                out[0] = (float)(((double)total / FIX_SCALE) / (double)N_ELEMS);
                d_accum = 0ULL;        // restore invariants for next replay
                d_done  = 0;
                __threadfence();
            }
        }
    }
}

// ---------------------------------------------------------------------------
extern "C" void kernel_launch(void* const* d_in, const int* in_sizes, int n_in,
                              void* d_out, int out_size) {
    const float* logits  = (const float*)d_in[0];
    const float* targets = (const float*)d_in[1];
    float* out = (float*)d_out;

    cudaFuncSetAttribute(ghm_fused, cudaFuncAttributeMaxDynamicSharedMemorySize,
                         SMEM_TOTAL_BYTES);
    ghm_fused<<<NCTA, TPB, SMEM_TOTAL_BYTES>>>(logits, targets, out);
}

// round 17
// speedup vs baseline: 1.0017x; 1.0017x over previous
#include <cuda_runtime.h>
#include <math.h>

#define N_ELEMS 16384
#define NBINS   4096
#define NCTA    64
#define TPB     256
#define BPT     (NBINS / TPB)          // 16 bins per thread
#define VPT     (N_ELEMS / 4 / TPB)    // 16 float4 per thread in bulk pass
#define DELTA_F 0.1f
#define EPS_F   1e-12f
#define FIX_SCALE 4294967296.0         // 2^32

// Dynamic smem layout (128B-aligned sections)
#define PREF_OFF 0                      // (NBINS+8) ints
#define CURS_OFF 16512                  // NBINS ints
#define G_OFF    32896                  // N_ELEMS floats
#define SORT_OFF 98432                  // N_ELEMS floats
#define SMEM_TOTAL_BYTES (SORT_OFF + N_ELEMS * 4)   // 163968 B

// ---- cross-CTA state: ONLY the commutative final reduce -------------------
__device__ unsigned long long d_accum;        // invariant: zero at launch entry
__device__ int   d_done;                      // invariant: zero at launch entry

__device__ __forceinline__ int warp_iscan(int v) {
#pragma unroll
    for (int o = 1; o < 32; o <<= 1) {
        int n = __shfl_up_sync(0xffffffffu, v, o);
        if ((threadIdx.x & 31) >= o) v += n;
    }
    return v;
}

__device__ __forceinline__ float sigmoid_g(float x, float tv) {
    return fabsf(1.0f / (1.0f + __expf(-x)) - tv);
}

__global__ __launch_bounds__(TPB)
void ghm_nosync(const float* __restrict__ logits,
                const float* __restrict__ targets,
                float* __restrict__ out) {
    extern __shared__ char smem[];
    int*   s_pref   = (int*)(smem + PREF_OFF);   // hist -> exclusive prefix
    int*   s_curs   = (int*)(smem + CURS_OFF);   // scatter cursors
    float* s_g      = (float*)(smem + G_OFF);    // all 16K g values
    float* s_sorted = (float*)(smem + SORT_OFF); // bin-sorted g values
    __shared__ int s_wsum[8];
    __shared__ unsigned long long s_acc[8];

    const int t   = threadIdx.x;
    const int bid = blockIdx.x;
    const int i   = bid * TPB + t;     // this thread owns element i

    // zero local histogram
    {
        int4 z = make_int4(0, 0, 0, 0);
#pragma unroll
        for (int k = 0; k < NBINS / 4 / TPB; k++)       // 4 x STS.128
            ((int4*)s_pref)[k * TPB + t] = z;
    }
    // own element: issue loads early (consumed after the bulk pass)
    float x_own = logits[i];
    float t_own = targets[i];
    __syncthreads();

    // ---- bulk pass: EVERY CTA computes all 16K g values locally ----
    // (redundant compute replaces the grid barrier + global g round-trip)
    const float4* lv = (const float4*)logits;
    const float4* tvv = (const float4*)targets;
#pragma unroll 4
    for (int k = 0; k < VPT; k++) {
        int v = k * TPB + t;
        float4 xs = lv[v];
        float4 ts = tvv[v];
        float g0 = sigmoid_g(xs.x, ts.x);
        float g1 = sigmoid_g(xs.y, ts.y);
        float g2 = sigmoid_g(xs.z, ts.z);
        float g3 = sigmoid_g(xs.w, ts.w);
        ((float4*)s_g)[v] = make_float4(g0, g1, g2, g3);
        atomicAdd(&s_pref[min((int)(g0 * (float)NBINS), NBINS - 1)], 1);
        atomicAdd(&s_pref[min((int)(g1 * (float)NBINS), NBINS - 1)], 1);
        atomicAdd(&s_pref[min((int)(g2 * (float)NBINS), NBINS - 1)], 1);
        atomicAdd(&s_pref[min((int)(g3 * (float)NBINS), NBINS - 1)], 1);
    }
    __syncthreads();

    // ---- local scan: in-place exclusive prefix; cursor copy ----
    {
        int h[BPT];
        const int4* hv = (const int4*)&s_pref[t * BPT];
#pragma unroll
        for (int q = 0; q < BPT / 4; q++) {             // 4 x LDS.128
            int4 a = hv[q];
            h[q * 4 + 0] = a.x; h[q * 4 + 1] = a.y;
            h[q * 4 + 2] = a.z; h[q * 4 + 3] = a.w;
        }
        int tot = 0;
#pragma unroll
        for (int k = 0; k < BPT; k++) tot += h[k];
        int incl = warp_iscan(tot);
        if ((t & 31) == 31) s_wsum[t >> 5] = incl;
        __syncthreads();
        if (t < 8) {
            int w = s_wsum[t];
#pragma unroll
            for (int o = 1; o < 8; o <<= 1) {
                int n = __shfl_up_sync(0xffu, w, o);
                if (t >= o) w += n;
            }
            s_wsum[t] = w;
        }
        __syncthreads();
        int base = incl - tot + ((t >> 5) ? s_wsum[(t >> 5) - 1] : 0);
#pragma unroll
        for (int q = 0; q < BPT / 4; q++) {
            int4 pr;
            pr.x = base;               base += h[q * 4 + 0];
            pr.y = base;               base += h[q * 4 + 1];
            pr.z = base;               base += h[q * 4 + 2];
            pr.w = base;               base += h[q * 4 + 3];
            ((int4*)&s_pref[t * BPT])[q] = pr;          // overwrite own bins
            ((int4*)&s_curs[t * BPT])[q] = pr;          // cursor copy
        }
        if (t == TPB - 1) s_pref[NBINS] = N_ELEMS;
    }
    __syncthreads();

    // ---- local scatter into bin-sorted smem array ----
#pragma unroll 4
    for (int k = 0; k < VPT; k++) {
        float4 gs = ((const float4*)s_g)[k * TPB + t];
        int b0 = min((int)(gs.x * (float)NBINS), NBINS - 1);
        int b1 = min((int)(gs.y * (float)NBINS), NBINS - 1);
        int b2 = min((int)(gs.z * (float)NBINS), NBINS - 1);
        int b3 = min((int)(gs.w * (float)NBINS), NBINS - 1);
        s_sorted[atomicAdd(&s_curs[b0], 1)] = gs.x;
        s_sorted[atomicAdd(&s_curs[b1], 1)] = gs.y;
        s_sorted[atomicAdd(&s_curs[b2], 1)] = gs.z;
        s_sorted[atomicAdd(&s_curs[b3], 1)] = gs.w;
    }
    __syncthreads();

    // ---- query own element ----
    // Interior bins [loBin+3, hiBin-3] guaranteed all-pass (>=1 bin-width
    // margin vs fp32 compare fuzz); bins outside [loBin-2, hiBin+2] guaranteed
    // all-fail; edge windows checked with the reference's exact fp32 compare.
    float g    = s_g[i];               // bulk-computed bits (identical expr)
    float loss = fmaxf(x_own, 0.0f) - x_own * t_own
               + log1pf(__expf(-fabsf(x_own)));
    unsigned long long fixterm;
    {
        float p = g * (float)NBINS;
        int loBin = (int)floorf(p - 0.1f * (float)NBINS);
        int hiBin = (int)floorf(p + 0.1f * (float)NBINS);

        int iLo = min(max(loBin + 3, 0), NBINS);
        int iHi = min(max(hiBin - 2, 0), NBINS);
        int cnt = (iHi > iLo) ? (s_pref[iHi] - s_pref[iLo]) : 0;

        int a0 = max(loBin - 2, 0), b0 = min(loBin + 2, NBINS - 1);
        if (b0 >= a0) {
            int s = s_pref[a0], e = s_pref[b0 + 1];
#pragma unroll 8
            for (int idx = s; idx < e; idx++)
                cnt += (fabsf(s_sorted[idx] - g) <= DELTA_F) ? 1 : 0;
        }
        int a1 = max(hiBin - 2, 0), b1 = min(hiBin + 2, NBINS - 1);
        if (b1 >= a1) {
            int s = s_pref[a1], e = s_pref[b1 + 1];
#pragma unroll 8
            for (int idx = s; idx < e; idx++)
                cnt += (fabsf(s_sorted[idx] - g) <= DELTA_F) ? 1 : 0;
        }

        float GD   = (float)cnt / DELTA_F;
        float beta = (float)N_ELEMS / (GD + EPS_F);
        float term = beta * loss;      // >= 0
        fixterm = (unsigned long long)((double)term * FIX_SCALE);
    }

    // ---- deterministic finalize (u64 fixed-point; flat ticket) ----
    {
        unsigned long long v = fixterm;
#pragma unroll
        for (int off = 16; off > 0; off >>= 1)
            v += __shfl_down_sync(0xffffffffu, v, off);
        if ((t & 31) == 0) s_acc[t >> 5] = v;
        __syncthreads();
        if (t == 0) {
            unsigned long long w = 0;
#pragma unroll
            for (int k = 0; k < TPB / 32; k++) w += s_acc[k];
            atomicAdd(&d_accum, w);
            __threadfence();
            if (atomicAdd(&d_done, 1) == NCTA - 1) {
                __threadfence();
                unsigned long long total = atomicAdd(&d_accum, 0ULL);
                out[0] = (float)(((double)total / FIX_SCALE) / (double)N_ELEMS);
                d_accum = 0ULL;        // restore invariants for next replay
                d_done  = 0;
                __threadfence();
            }
        }
    }
}

// ---------------------------------------------------------------------------
extern "C" void kernel_launch(void* const* d_in, const int* in_sizes, int n_in,
                              void* d_out, int out_size) {
    const float* logits  = (const float*)d_in[0];
    const float* targets = (const float*)d_in[1];
    float* out = (float*)d_out;

    cudaFuncSetAttribute(ghm_nosync, cudaFuncAttributeMaxDynamicSharedMemorySize,
                         SMEM_TOTAL_BYTES);
    ghm_nosync<<<NCTA, TPB, SMEM_TOTAL_BYTES>>>(logits, targets, out);
}